// round 6
// baseline (speedup 1.0000x reference)
#include <cuda_runtime.h>
#include <cstdint>

// Problem constants (from reference)
#define N_NODES 2000000
#define N_EDGES 32000000
#define N_OUT   400000   // N_NODES / 5

// Scratch: aggregation slots only for nodes with idx % 5 == 0 (1.6 MB, L2-resident)
__device__ float g_agg[N_OUT];

// --------------------------------------------------------------------------
// Kernel 1: zero the aggregation scratch (graph replays re-run all work).
// --------------------------------------------------------------------------
__global__ void zero_agg_kernel() {
    int i = blockIdx.x * blockDim.x + threadIdx.x;
    if (i < N_OUT) g_agg[i] = 0.0f;
}

// --------------------------------------------------------------------------
// Kernel 2: edge scatter. edge_index is INT32 (JAX x64-disabled downgrades
// int64 -> int32). Stream dst (filter %5), gather x[src] (L2-resident 8 MB),
// atomicAdd into g_agg[dst/5]. 4 edges/thread via int4 loads.
// --------------------------------------------------------------------------
__global__ void scatter_kernel(const float* __restrict__ x,
                               const int* __restrict__ src,
                               const int* __restrict__ dst) {
    long long base = (long long)(blockIdx.x * (long long)blockDim.x + threadIdx.x) * 4;
    if (base >= N_EDGES) return;

    int4 dv = *reinterpret_cast<const int4*>(dst + base);
    int4 sv = *reinterpret_cast<const int4*>(src + base);

    int d[4] = { dv.x, dv.y, dv.z, dv.w };
    int s[4] = { sv.x, sv.y, sv.z, sv.w };

#pragma unroll
    for (int k = 0; k < 4; k++) {
        if (d[k] % 5 == 0) {
            float v = __ldg(x + s[k]);            // x[src] — L2 hit after first touch
            atomicAdd(&g_agg[d[k] / 5], v);       // no return -> REDG to L2
        }
    }
}

// --------------------------------------------------------------------------
// Kernel 3: finalize. a = agg*w_conv + b_conv; collapsed scalar MLP; write out.
// --------------------------------------------------------------------------
__global__ void finalize_kernel(const float* __restrict__ w_conv,
                                const float* __restrict__ b_conv,
                                const float* __restrict__ w1,
                                const float* __restrict__ b1,
                                const float* __restrict__ w2,
                                const float* __restrict__ b2,
                                float* __restrict__ out) {
    int i = blockIdx.x * blockDim.x + threadIdx.x;
    if (i >= N_OUT) return;

    float wc = __ldg(w_conv);
    float bc = __ldg(b_conv);
    float a = fmaf(g_agg[i], wc, bc);

    float acc = __ldg(b2);
#pragma unroll
    for (int j = 0; j < 4; j++) {
        // w1 stored [in=2, out=4] row-major: row0 then row1
        float weff = __ldg(w1 + j) + __ldg(w1 + 4 + j);
        float t = fmaxf(fmaf(a, weff, __ldg(b1 + j)), 0.0f);
        acc = fmaf(t, __ldg(w2 + j), acc);
    }
    out[i] = acc;
}

// --------------------------------------------------------------------------
// Launch
// inputs per metadata order:
//   d_in[0] x          (2,000,000 f32)
//   d_in[1] edge_index (2 x 32,000,000 int32, row-major: src row then dst row)
//   d_in[2] w_conv (1)  d_in[3] b_conv (1)
//   d_in[4] w1 (8)      d_in[5] b1 (4)
//   d_in[6] w2 (4)      d_in[7] b2 (1)
// output: 400,000 f32
// --------------------------------------------------------------------------
extern "C" void kernel_launch(void* const* d_in, const int* in_sizes, int n_in,
                              void* d_out, int out_size) {
    const float* x   = (const float*)d_in[0];
    const int*   ei  = (const int*)d_in[1];
    const int*   src = ei;
    const int*   dst = ei + N_EDGES;
    const float* w_conv = (const float*)d_in[2];
    const float* b_conv = (const float*)d_in[3];
    const float* w1     = (const float*)d_in[4];
    const float* b1     = (const float*)d_in[5];
    const float* w2     = (const float*)d_in[6];
    const float* b2     = (const float*)d_in[7];
    float* out = (float*)d_out;

    {
        int threads = 256;
        int blocks = (N_OUT + threads - 1) / threads;
        zero_agg_kernel<<<blocks, threads>>>();
    }
    {
        int threads = 256;
        long long work = (long long)N_EDGES / 4;            // 8M threads, 4 edges each
        int blocks = (int)((work + threads - 1) / threads); // 31250
        scatter_kernel<<<blocks, threads>>>(x, src, dst);
    }
    {
        int threads = 256;
        int blocks = (N_OUT + threads - 1) / threads;
        finalize_kernel<<<blocks, threads>>>(w_conv, b_conv, w1, b1, w2, b2, out);
    }
}